// round 10
// baseline (speedup 1.0000x reference)
#include <cuda_runtime.h>

#define INPUT_SIZE     32768
#define NUM_COLS       4096
#define NUM_ACTIVE     82
#define THREADS        256
#define ROWS_PER_BLOCK 2
#define NBLOCKS        (NUM_COLS / ROWS_PER_BLOCK)   // 2048
#define COMPACT_BLOCKS 128
#define SMEM_IDX_CAP   2048
#define HIST_BINS      2048

// Scratch (allocation-free rule). Zero-initialized at module load; flags reset
// by the elected block at the end of each call -> graph replays deterministic.
__device__ int          g_count;
__device__ volatile int g_ready;
__device__ int          g_done;
__device__ int          g_indices[INPUT_SIZE];
__device__ float        g_boosted[NUM_COLS];

// ---------------------------------------------------------------------------
// ONE fused kernel (R7 scattered-gather structure, occupancy-tuned):
//   Phase A (blocks 0..127): ballot-compact on-bit indices of input_vector.
//   Phase B (all blocks): spin on flag, stage indices in SMEM, gather 2 rows
//     each with 8 independent 4B load streams. __launch_bounds__(256,7)
//     -> <=36 regs -> 7 blocks/SM (~87% occ) -> ~2x outstanding loads vs R7,
//     which was MLP-starved at 4 blocks/SM (DRAM 75%, issue 2.9%).
//   Phase C (last-finishing block): 2048-bin histogram top-k over the exact
//     integer overlaps, register-lean (reloads g_boosted from L2 per pass);
//     stable tie-break by column index == jax.lax.top_k order; writes both
//     output segments; resets flags.
// All sums are exact small-integer commutative reductions -> output invariant
// to the nondeterministic compaction order (bit-exact vs reference).
// ---------------------------------------------------------------------------
__global__ __launch_bounds__(THREADS, 7)
void fused_kernel(const float* __restrict__ in,
                  const float* __restrict__ conn,
                  const float* __restrict__ boost,
                  float* __restrict__ out) {
    __shared__ int   buf[SMEM_IDX_CAP];  // B: sidx; C: 2048-bin histogram
    __shared__ int   s_n;
    __shared__ int   wsum[8];
    __shared__ int   sbase;
    __shared__ float wred[16];
    __shared__ int   s_elected;
    __shared__ int   sT, sR;
    __shared__ int   scan_tmp[THREADS];

    const int tid  = threadIdx.x;
    const int bid  = blockIdx.x;
    const int lane = tid & 31;
    const int warp = tid >> 5;

    // ================= Phase A: compaction (blocks 0..127) ================
    if (bid < COMPACT_BLOCKS) {
        const int idx = bid * 256 + tid;
        const bool on = (in[idx] != 0.0f);
        const unsigned m = __ballot_sync(0xffffffffu, on);
        if (lane == 0) wsum[warp] = __popc(m);
        __syncthreads();
        if (tid == 0) {
            int acc = 0;
#pragma unroll
            for (int w = 0; w < 8; w++) { int c = wsum[w]; wsum[w] = acc; acc += c; }
            sbase = atomicAdd(&g_count, acc);         // reserve output slice
        }
        __syncthreads();
        if (on) {
            const int pos = sbase + wsum[warp] + __popc(m & ((1u << lane) - 1u));
            g_indices[pos] = idx;
        }
        __threadfence();
        __syncthreads();                              // all stores published
        if (tid == 0) atomicAdd((int*)&g_ready, 1);
    }

    // ================= Wait for compaction =================
    if (tid == 0) {
        while (*(volatile int*)&g_ready < COMPACT_BLOCKS) __nanosleep(64);
        __threadfence();
        s_n = *(volatile int*)&g_count;
    }
    __syncthreads();
    const int n = s_n;

    // ================= Phase B: stage indices + gather 2 rows =============
    const int n_s = (n < SMEM_IDX_CAP) ? n : SMEM_IDX_CAP;
    for (int k = tid; k < n_s; k += THREADS) buf[k] = g_indices[k];
    __syncthreads();

    const int r = bid * ROWS_PER_BLOCK;
    const float* __restrict__ row0 = conn + (size_t)r * INPUT_SIZE;
    const float* __restrict__ row1 = row0 + INPUT_SIZE;

    float a0 = 0.f, a1 = 0.f, a2 = 0.f, a3 = 0.f;
    float b0 = 0.f, b1 = 0.f, b2 = 0.f, b3 = 0.f;
    int k = tid;
    for (; k + 3 * THREADS < n_s; k += 4 * THREADS) {
        int i0 = buf[k];
        int i1 = buf[k +     THREADS];
        int i2 = buf[k + 2 * THREADS];
        int i3 = buf[k + 3 * THREADS];
        a0 += __ldcs(row0 + i0);  b0 += __ldcs(row1 + i0);
        a1 += __ldcs(row0 + i1);  b1 += __ldcs(row1 + i1);
        a2 += __ldcs(row0 + i2);  b2 += __ldcs(row1 + i2);
        a3 += __ldcs(row0 + i3);  b3 += __ldcs(row1 + i3);
    }
    for (; k < n_s; k += THREADS) {
        int i = buf[k];
        a0 += __ldcs(row0 + i);  b0 += __ldcs(row1 + i);
    }
    for (int k2 = SMEM_IDX_CAP + tid; k2 < n; k2 += THREADS) {  // safety tail
        int i = g_indices[k2];
        a0 += __ldcs(row0 + i);  b0 += __ldcs(row1 + i);
    }
    float sa = (a0 + a1) + (a2 + a3);
    float sb = (b0 + b1) + (b2 + b3);

    // ---- Block reduce both rows ----
#pragma unroll
    for (int dd = 16; dd; dd >>= 1) {
        sa += __shfl_down_sync(0xffffffffu, sa, dd);
        sb += __shfl_down_sync(0xffffffffu, sb, dd);
    }
    if (lane == 0) { wred[warp] = sa; wred[8 + warp] = sb; }
    __syncthreads();

    if (tid == 0) {
        float t0 = 0.f, t1 = 0.f;
#pragma unroll
        for (int w = 0; w < 8; w++) { t0 += wred[w]; t1 += wred[8 + w]; }
        g_boosted[r]     = t0 * __ldg(&boost[r]);
        g_boosted[r + 1] = t1 * __ldg(&boost[r + 1]);
        __threadfence();
        int ticket = atomicAdd(&g_done, 1);
        s_elected = (ticket == NBLOCKS - 1) ? 1 : 0;
    }
    __syncthreads();

    // ================= Phase C: top-k (elected block only) =================
    // Register-lean: each pass reloads g_boosted from L2 (__ldcg, ~16KB/pass).
    if (s_elected) {
        if (tid == 0) __threadfence();   // acquire: see all g_boosted writes
        __syncthreads();

        // Pass 1: zero histogram (8 bins/thread), populate.
#pragma unroll
        for (int i = 0; i < 8; i++) buf[tid * 8 + i] = 0;
        __syncthreads();
        for (int j = tid; j < NUM_COLS; j += THREADS) {
            int t = (int)__ldcg(&g_boosted[j]);       // exact small integers
            if (t >= HIST_BINS) t = HIST_BINS - 1;
            atomicAdd(&buf[t], 1);
        }
        __syncthreads();

        // Per-thread bin-sum over owned bins [8*tid, 8*tid+8).
        int s = 0;
#pragma unroll
        for (int i = 0; i < 8; i++) s += buf[tid * 8 + i];

        // Suffix scan: above = sum of bins owned by higher tids.
        scan_tmp[255 - tid] = s;
        __syncthreads();
        {
            int x = scan_tmp[tid];
#pragma unroll
            for (int d = 1; d < 32; d <<= 1) {
                int y = __shfl_up_sync(0xffffffffu, x, d);
                if (lane >= d) x += y;                // inclusive warp scan
            }
            if (lane == 31) wsum[warp] = x;
            __syncthreads();
            if (tid == 0) {
                int acc = 0;
#pragma unroll
                for (int w = 0; w < 8; w++) { int c = wsum[w]; wsum[w] = acc; acc += c; }
            }
            __syncthreads();
            int excl = wsum[warp] + x - scan_tmp[tid];
            __syncthreads();
            scan_tmp[255 - tid] = excl;
        }
        __syncthreads();
        const int above = scan_tmp[tid];

        // Locate threshold bin T (unique: GE >= K > GT) and residue R.
        {
            int running = above;
            for (int bin = tid * 8 + 7; bin >= tid * 8; --bin) {
                int cb = buf[bin];
                if (running < NUM_ACTIVE && running + cb >= NUM_ACTIVE) {
                    sT = bin;
                    sR = NUM_ACTIVE - running;        // ties to take, index order
                }
                running += cb;
            }
        }
        __syncthreads();
        const int T = sT, R = sR;

        // Pass 2: per-thread tie counts over my 16 contiguous columns.
        const int cbase = tid * 16;
        int eq = 0;
#pragma unroll 4
        for (int i = 0; i < 16; i++) {
            int t = (int)__ldcg(&g_boosted[cbase + i]);
            if (t >= HIST_BINS) t = HIST_BINS - 1;
            eq += (t == T) ? 1 : 0;
        }
        int run;
        {
            int x = eq;
#pragma unroll
            for (int d = 1; d < 32; d <<= 1) {
                int y = __shfl_up_sync(0xffffffffu, x, d);
                if (lane >= d) x += y;
            }
            if (lane == 31) wsum[warp] = x;
            __syncthreads();
            if (tid == 0) {
                int acc = 0;
#pragma unroll
                for (int w = 0; w < 8; w++) { int c = wsum[w]; wsum[w] = acc; acc += c; }
            }
            __syncthreads();
            run = wsum[warp] + x - eq;                // exclusive tie prefix
        }

        // Pass 3: decide winners float4-at-a-time, write both segments.
        const float4* gb4 = reinterpret_cast<const float4*>(g_boosted);
        float4* o0 = reinterpret_cast<float4*>(out + cbase);
        float4* o1 = reinterpret_cast<float4*>(out + NUM_COLS + cbase);
#pragma unroll
        for (int i = 0; i < 4; i++) {
            float4 f = __ldcg(&gb4[tid * 4 + i]);
            float vv[4] = {f.x, f.y, f.z, f.w};
            float mk[4], mv[4];
#pragma unroll
            for (int q = 0; q < 4; q++) {
                int t = (int)vv[q];
                if (t >= HIST_BINS) t = HIST_BINS - 1;
                bool win;
                if (t > T)       win = true;
                else if (t == T) { win = (run < R); run++; }
                else             win = false;
                mk[q] = win ? 1.0f  : 0.0f;
                mv[q] = win ? vv[q] : 0.0f;
            }
            o0[i] = make_float4(mk[0], mk[1], mk[2], mk[3]);
            o1[i] = make_float4(mv[0], mv[1], mv[2], mv[3]);
        }

        // Reset flags for the next graph replay.
        if (tid == 0) { g_count = 0; g_ready = 0; g_done = 0; }
    }
}

// ---------------------------------------------------------------------------
extern "C" void kernel_launch(void* const* d_in, const int* in_sizes, int n_in,
                              void* d_out, int out_size) {
    const float* inp   = nullptr;
    const float* conn  = nullptr;
    const float* boost = nullptr;
    for (int i = 0; i < n_in; i++) {
        if (in_sizes[i] == INPUT_SIZE)      inp   = (const float*)d_in[i];
        else if (in_sizes[i] == NUM_COLS)   boost = (const float*)d_in[i];
        else                                conn  = (const float*)d_in[i];
    }
    float* out = (float*)d_out;
    (void)out_size; (void)n_in;

    fused_kernel<<<NBLOCKS, THREADS>>>(inp, conn, boost, out);
}

// round 11
// speedup vs baseline: 1.0129x; 1.0129x over previous
#include <cuda_runtime.h>

#define INPUT_SIZE     32768
#define NUM_COLS       4096
#define NUM_ACTIVE     82
#define THREADS        256
#define ROWS_PER_BLOCK 8
#define NBLOCKS        (NUM_COLS / ROWS_PER_BLOCK)   // 512
#define COMPACT_BLOCKS 128
#define SMEM_IDX_CAP   2048
#define HIST_BINS      2048

// Scratch (allocation-free rule). Zero-initialized at module load; flags reset
// by the elected block at the end of each call -> graph replays deterministic.
__device__ int          g_count;
__device__ volatile int g_ready;
__device__ int          g_done;
__device__ int          g_indices[INPUT_SIZE];
__device__ float        g_boosted[NUM_COLS];

// ---------------------------------------------------------------------------
// ONE fused kernel, stream-locality tuned:
//   Phase A (blocks 0..127): ballot-compact on-bit indices of input_vector.
//   Phase B (512 blocks): stage indices once, then process 8 contiguous rows
//     as 4 sequential row-PAIRS. Only ~1024 concurrent row-streams chip-wide
//     (vs ~2400 in the R7 config) -> better DRAM row-buffer locality. Per
//     pair: strided sorted gather (2-deep idx unroll -> 4 independent LDGs in
//     flight), warp shfl-reduce into private smem slots with NO per-pair
//     block sync (warps skew across pairs, overlapping reduce latency with
//     the next pair's loads). One __syncthreads at the end, 8 writes.
//   Phase C (last-finishing block): register-lean 2048-bin histogram top-k
//     over the exact integer overlaps; stable tie-break by column index ==
//     jax.lax.top_k order; writes both output segments; resets flags.
// All sums are exact small-integer commutative reductions -> output invariant
// to the nondeterministic compaction order (bit-exact vs reference).
// ---------------------------------------------------------------------------
__global__ __launch_bounds__(THREADS, 4)
void fused_kernel(const float* __restrict__ in,
                  const float* __restrict__ conn,
                  const float* __restrict__ boost,
                  float* __restrict__ out) {
    __shared__ int   buf[SMEM_IDX_CAP];  // B: sidx; C: 2048-bin histogram
    __shared__ int   s_n;
    __shared__ int   wsum[8];
    __shared__ int   sbase;
    __shared__ float wpart[ROWS_PER_BLOCK][8];
    __shared__ int   s_elected;
    __shared__ int   sT, sR;
    __shared__ int   scan_tmp[THREADS];

    const int tid  = threadIdx.x;
    const int bid  = blockIdx.x;
    const int lane = tid & 31;
    const int warp = tid >> 5;

    // ================= Phase A: compaction (blocks 0..127) ================
    if (bid < COMPACT_BLOCKS) {
        const int idx = bid * 256 + tid;
        const bool on = (in[idx] != 0.0f);
        const unsigned m = __ballot_sync(0xffffffffu, on);
        if (lane == 0) wsum[warp] = __popc(m);
        __syncthreads();
        if (tid == 0) {
            int acc = 0;
#pragma unroll
            for (int w = 0; w < 8; w++) { int c = wsum[w]; wsum[w] = acc; acc += c; }
            sbase = atomicAdd(&g_count, acc);         // reserve output slice
        }
        __syncthreads();
        if (on) {
            const int pos = sbase + wsum[warp] + __popc(m & ((1u << lane) - 1u));
            g_indices[pos] = idx;
        }
        __threadfence();
        __syncthreads();                              // all stores published
        if (tid == 0) atomicAdd((int*)&g_ready, 1);
    }

    // ================= Wait for compaction =================
    if (tid == 0) {
        while (*(volatile int*)&g_ready < COMPACT_BLOCKS) __nanosleep(64);
        __threadfence();
        s_n = *(volatile int*)&g_count;
    }
    __syncthreads();
    const int n = s_n;

    // ================= Phase B: stage indices once =================
    const int n_s = (n < SMEM_IDX_CAP) ? n : SMEM_IDX_CAP;
    for (int k = tid; k < n_s; k += THREADS) buf[k] = g_indices[k];
    __syncthreads();

    // ---- 8 rows as 4 sequential pairs; no block sync between pairs ----
    const int r0 = bid * ROWS_PER_BLOCK;
#pragma unroll
    for (int p = 0; p < ROWS_PER_BLOCK / 2; p++) {
        const float* __restrict__ rowA = conn + (size_t)(r0 + 2 * p) * INPUT_SIZE;
        const float* __restrict__ rowB = rowA + INPUT_SIZE;

        float a0 = 0.f, a1 = 0.f, b0 = 0.f, b1 = 0.f;
        int k = tid;
        for (; k + THREADS < n_s; k += 2 * THREADS) {
            int i0 = buf[k];
            int i1 = buf[k + THREADS];
            a0 += __ldcs(rowA + i0);  b0 += __ldcs(rowB + i0);
            a1 += __ldcs(rowA + i1);  b1 += __ldcs(rowB + i1);
        }
        if (k < n_s) {
            int i = buf[k];
            a0 += __ldcs(rowA + i);  b0 += __ldcs(rowB + i);
        }
        for (int k2 = SMEM_IDX_CAP + tid; k2 < n; k2 += THREADS) {  // safety
            int i = g_indices[k2];
            a0 += __ldcs(rowA + i);  b0 += __ldcs(rowB + i);
        }
        float sa = a0 + a1;
        float sb = b0 + b1;
#pragma unroll
        for (int d = 16; d; d >>= 1) {
            sa += __shfl_down_sync(0xffffffffu, sa, d);
            sb += __shfl_down_sync(0xffffffffu, sb, d);
        }
        if (lane == 0) {                 // private slot per warp: no sync needed
            wpart[2 * p][warp]     = sa;
            wpart[2 * p + 1][warp] = sb;
        }
    }
    __syncthreads();

    if (tid < ROWS_PER_BLOCK) {
        float t = 0.f;
#pragma unroll
        for (int w = 0; w < 8; w++) t += wpart[tid][w];
        g_boosted[r0 + tid] = t * __ldg(&boost[r0 + tid]);
        __threadfence();                 // each writer publishes its own store
    }
    __syncthreads();
    if (tid == 0) {
        int ticket = atomicAdd(&g_done, 1);
        s_elected = (ticket == NBLOCKS - 1) ? 1 : 0;
    }
    __syncthreads();

    // ================= Phase C: top-k (elected block only) =================
    // Register-lean: each pass reloads g_boosted from L2 (__ldcg, ~16KB/pass).
    if (s_elected) {
        if (tid == 0) __threadfence();   // acquire: see all g_boosted writes
        __syncthreads();

        // Pass 1: zero histogram (8 bins/thread), populate.
#pragma unroll
        for (int i = 0; i < 8; i++) buf[tid * 8 + i] = 0;
        __syncthreads();
        for (int j = tid; j < NUM_COLS; j += THREADS) {
            int t = (int)__ldcg(&g_boosted[j]);       // exact small integers
            if (t >= HIST_BINS) t = HIST_BINS - 1;
            atomicAdd(&buf[t], 1);
        }
        __syncthreads();

        // Per-thread bin-sum over owned bins [8*tid, 8*tid+8).
        int s = 0;
#pragma unroll
        for (int i = 0; i < 8; i++) s += buf[tid * 8 + i];

        // Suffix scan: above = sum of bins owned by higher tids.
        scan_tmp[255 - tid] = s;
        __syncthreads();
        {
            int x = scan_tmp[tid];
#pragma unroll
            for (int d = 1; d < 32; d <<= 1) {
                int y = __shfl_up_sync(0xffffffffu, x, d);
                if (lane >= d) x += y;                // inclusive warp scan
            }
            if (lane == 31) wsum[warp] = x;
            __syncthreads();
            if (tid == 0) {
                int acc = 0;
#pragma unroll
                for (int w = 0; w < 8; w++) { int c = wsum[w]; wsum[w] = acc; acc += c; }
            }
            __syncthreads();
            int excl = wsum[warp] + x - scan_tmp[tid];
            __syncthreads();
            scan_tmp[255 - tid] = excl;
        }
        __syncthreads();
        const int above = scan_tmp[tid];

        // Locate threshold bin T (unique: GE >= K > GT) and residue R.
        {
            int running = above;
            for (int bin = tid * 8 + 7; bin >= tid * 8; --bin) {
                int cb = buf[bin];
                if (running < NUM_ACTIVE && running + cb >= NUM_ACTIVE) {
                    sT = bin;
                    sR = NUM_ACTIVE - running;        // ties to take, index order
                }
                running += cb;
            }
        }
        __syncthreads();
        const int T = sT, R = sR;

        // Pass 2: per-thread tie counts over my 16 contiguous columns.
        const int cbase = tid * 16;
        int eq = 0;
#pragma unroll 4
        for (int i = 0; i < 16; i++) {
            int t = (int)__ldcg(&g_boosted[cbase + i]);
            if (t >= HIST_BINS) t = HIST_BINS - 1;
            eq += (t == T) ? 1 : 0;
        }
        int run;
        {
            int x = eq;
#pragma unroll
            for (int d = 1; d < 32; d <<= 1) {
                int y = __shfl_up_sync(0xffffffffu, x, d);
                if (lane >= d) x += y;
            }
            if (lane == 31) wsum[warp] = x;
            __syncthreads();
            if (tid == 0) {
                int acc = 0;
#pragma unroll
                for (int w = 0; w < 8; w++) { int c = wsum[w]; wsum[w] = acc; acc += c; }
            }
            __syncthreads();
            run = wsum[warp] + x - eq;                // exclusive tie prefix
        }

        // Pass 3: decide winners float4-at-a-time, write both segments.
        const float4* gb4 = reinterpret_cast<const float4*>(g_boosted);
        float4* o0 = reinterpret_cast<float4*>(out + cbase);
        float4* o1 = reinterpret_cast<float4*>(out + NUM_COLS + cbase);
#pragma unroll
        for (int i = 0; i < 4; i++) {
            float4 f = __ldcg(&gb4[tid * 4 + i]);
            float vv[4] = {f.x, f.y, f.z, f.w};
            float mk[4], mv[4];
#pragma unroll
            for (int q = 0; q < 4; q++) {
                int t = (int)vv[q];
                if (t >= HIST_BINS) t = HIST_BINS - 1;
                bool win;
                if (t > T)       win = true;
                else if (t == T) { win = (run < R); run++; }
                else             win = false;
                mk[q] = win ? 1.0f  : 0.0f;
                mv[q] = win ? vv[q] : 0.0f;
            }
            o0[i] = make_float4(mk[0], mk[1], mk[2], mk[3]);
            o1[i] = make_float4(mv[0], mv[1], mv[2], mv[3]);
        }

        // Reset flags for the next graph replay.
        if (tid == 0) { g_count = 0; g_ready = 0; g_done = 0; }
    }
}

// ---------------------------------------------------------------------------
extern "C" void kernel_launch(void* const* d_in, const int* in_sizes, int n_in,
                              void* d_out, int out_size) {
    const float* inp   = nullptr;
    const float* conn  = nullptr;
    const float* boost = nullptr;
    for (int i = 0; i < n_in; i++) {
        if (in_sizes[i] == INPUT_SIZE)      inp   = (const float*)d_in[i];
        else if (in_sizes[i] == NUM_COLS)   boost = (const float*)d_in[i];
        else                                conn  = (const float*)d_in[i];
    }
    float* out = (float*)d_out;
    (void)out_size; (void)n_in;

    fused_kernel<<<NBLOCKS, THREADS>>>(inp, conn, boost, out);
}